// round 16
// baseline (speedup 1.0000x reference)
#include <cuda_runtime.h>
#include <cuda_bf16.h>
#include <cuda_fp16.h>
#include <cstdint>
#include <cmath>

#define BS_     2
#define SEQ_    1024
#define DIM_    2048
#define H_      16
#define QRANK_  768
#define KVRANK_ 512
#define QS_     128
#define ROT_    64
#define CD_     576
#define VD_     128
#define T_      2048
#define QUP_    3072

typedef unsigned short u16;

__device__ float g_qd   [(size_t)T_ * QRANK_];
__device__ float g_kvraw[(size_t)T_ * CD_];
__device__ float g_qfull[(size_t)T_ * QUP_];
__device__ float g_scr  [(size_t)BS_ * H_ * SEQ_ * SEQ_];

#define DECL2(name, n) __device__ __align__(16) u16 name##h[(size_t)(n)]; \
                       __device__ __align__(16) u16 name##l[(size_t)(n)];
DECL2(s_x,    T_ * DIM_)                  // fp16
DECL2(s_qdw,  QRANK_ * DIM_)              // fp16
DECL2(s_quw,  QUP_ * QRANK_)              // fp16
DECL2(s_kdw,  CD_ * DIM_)                 // fp16
DECL2(s_ow,   DIM_ * DIM_)                // fp16
DECL2(s_kKT,  H_ * KVRANK_ * QS_)         // fp16
DECL2(s_kV,   H_ * VD_ * KVRANK_)         // fp16
DECL2(s_qn,   T_ * QRANK_)                // fp16
DECL2(s_qf,   T_ * QUP_)                  // fp16
DECL2(s_kf,   T_ * CD_)                   // bf16 (B of stage 5)
DECL2(s_kfT,  BS_ * KVRANK_ * SEQ_)       // fp16
DECL2(s_qa,   (size_t)BS_ * H_ * SEQ_ * CD_)    // bf16 (A of stage 5)
DECL2(s_P,    (size_t)BS_ * H_ * SEQ_ * SEQ_)   // fp16
DECL2(s_cc,   (size_t)BS_ * H_ * SEQ_ * KVRANK_)// fp16
DECL2(s_cx,   T_ * DIM_)                  // fp16

__device__ __forceinline__ uint32_t smem_u32(const void* p) {
    uint32_t a;
    asm("{ .reg .u64 t; cvta.to.shared.u64 t, %1; cvt.u32.u64 %0, t; }" : "=r"(a) : "l"(p));
    return a;
}
__device__ __forceinline__ void ldsm4(uint32_t* r, uint32_t addr) {
    asm volatile("ldmatrix.sync.aligned.m8n8.x4.shared.b16 {%0,%1,%2,%3}, [%4];"
        : "=r"(r[0]), "=r"(r[1]), "=r"(r[2]), "=r"(r[3]) : "r"(addr));
}
template<int FP16>
__device__ __forceinline__ void mmaT(float* c, const uint32_t* a, const uint32_t* b) {
    if (FP16)
        asm volatile("mma.sync.aligned.m16n8k16.row.col.f32.f16.f16.f32 "
            "{%0,%1,%2,%3}, {%4,%5,%6,%7}, {%8,%9}, {%0,%1,%2,%3};"
            : "+f"(c[0]), "+f"(c[1]), "+f"(c[2]), "+f"(c[3])
            : "r"(a[0]), "r"(a[1]), "r"(a[2]), "r"(a[3]), "r"(b[0]), "r"(b[1]));
    else
        asm volatile("mma.sync.aligned.m16n8k16.row.col.f32.bf16.bf16.f32 "
            "{%0,%1,%2,%3}, {%4,%5,%6,%7}, {%8,%9}, {%0,%1,%2,%3};"
            : "+f"(c[0]), "+f"(c[1]), "+f"(c[2]), "+f"(c[3])
            : "r"(a[0]), "r"(a[1]), "r"(a[2]), "r"(a[3]), "r"(b[0]), "r"(b[1]));
}
__device__ __forceinline__ void cpa16(uint32_t dst, const void* src, int sz) {
    asm volatile("cp.async.cg.shared.global [%0], [%1], 16, %2;"
        :: "r"(dst), "l"(src), "r"(sz) : "memory");
}
#define CP_COMMIT() asm volatile("cp.async.commit_group;" ::: "memory")
#define CP_WAIT1()  asm volatile("cp.async.wait_group 1;" ::: "memory")

template<int FP16>
__device__ __forceinline__ void split1T(float v, u16& h, u16& l) {
    if (FP16) {
        __half hb = __float2half_rn(v);
        h = __half_as_ushort(hb);
        l = __half_as_ushort(__float2half_rn(v - __half2float(hb)));
    } else {
        __nv_bfloat16 hb = __float2bfloat16(v);
        h = __bfloat16_as_ushort(hb);
        l = __bfloat16_as_ushort(__float2bfloat16(v - __bfloat162float(hb)));
    }
}
template<int FP16>
__device__ __forceinline__ void split4T(float4 v, uint64_t& hi, uint64_t& lo) {
    u16 h0,h1,h2,h3,l0,l1,l2,l3;
    split1T<FP16>(v.x,h0,l0); split1T<FP16>(v.y,h1,l1);
    split1T<FP16>(v.z,h2,l2); split1T<FP16>(v.w,h3,l3);
    hi = (uint64_t)h0 | ((uint64_t)h1<<16) | ((uint64_t)h2<<32) | ((uint64_t)h3<<48);
    lo = (uint64_t)l0 | ((uint64_t)l1<<16) | ((uint64_t)l2<<32) | ((uint64_t)l3<<48);
}

#define CS_LD   132

// derived per-config smem (host + device)
__host__ __device__ constexpr int cfg_kch(int passes)   { return passes == 2 ? 64 : 32; }
__host__ __device__ constexpr int cfg_spe(int passes)   { return passes == 2 ? 72 : 40; }
__host__ __device__ constexpr int cfg_nt(int passes)    { return passes == 2 ? 3 : 4; }
__host__ __device__ constexpr int cfg_stageb(int passes){ return cfg_nt(passes) * 128 * cfg_spe(passes) * 2; }
__host__ __device__ constexpr int cfg_smem(int passes)  {
    int s = 2 * cfg_stageb(passes);
    int e = 128 * CS_LD * 4;
    return s > e ? s : e;
}

// C = alpha * A x B^T + bias ; A:[M,K] hi/lo, B:[N,K] hi/lo, k-contiguous
// PASSES==3: Ah*Bh + Ah*Bl + Al*Bh (KC=32, 4 tiles)
// PASSES==2: Ah*Bh + Al*Bh         (KC=64, 3 tiles, Bl never loaded)
template<int FP16, int PASSES, int OUTF16>
__global__ __launch_bounds__(256, 2) void gemm_bf(
    const u16* __restrict__ Ah, const u16* __restrict__ Al,
    const u16* __restrict__ Bh, const u16* __restrict__ Bl,
    float* __restrict__ Cf, u16* __restrict__ Ch, u16* __restrict__ Cl,
    const float* __restrict__ bias,
    int M, int N, int K, int lda, int ldb, int ldc,
    long long sAo, long long sAi, long long sBo, long long sBi,
    long long sCo, long long sCi, int zdiv,
    float alpha, int causal, int klimit)
{
    constexpr int KCH   = cfg_kch(PASSES);
    constexpr int SPe   = cfg_spe(PASSES);
    constexpr int ROWB  = SPe * 2;
    constexpr int TILEB = 128 * ROWB;
    constexpr int STAGEB = cfg_stageb(PASSES);
    constexpr int OFFAH = 0, OFFAL = TILEB, OFFBH = 2 * TILEB, OFFBL = 3 * TILEB;
    constexpr int CHK   = KCH / 16;          // 16B chunks per thread per tile
    constexpr int KS    = KCH / 16;          // k16 steps per chunk

    int z = blockIdx.z;
    int zo = z / zdiv, zi = z - zo * zdiv;
    Ah += zo * sAo + zi * sAi;  Al += zo * sAo + zi * sAi;
    Bh += zo * sBo + zi * sBi;  if (PASSES == 3) Bl += zo * sBo + zi * sBi;
    long long co = zo * sCo + zi * sCi;
    if (Cf) Cf += co;
    if (Ch) { Ch += co; Cl += co; }

    int m0 = blockIdx.y * 128, n0 = blockIdx.x * 128;
    if (causal && n0 > m0) return;
    int kmax = klimit ? min(K, m0 + 128) : K;
    int nch = kmax / KCH;

    extern __shared__ char smem[];
    uint32_t sb = smem_u32(smem);
    int tid = threadIdx.x, wid = tid >> 5, lane = tid & 31;
    int wm = wid & 1, wn = wid >> 1;

    float acc[4][4][4];
#pragma unroll
    for (int i = 0; i < 4; i++)
#pragma unroll
        for (int j = 0; j < 4; j++)
#pragma unroll
            for (int q = 0; q < 4; q++) acc[i][j][q] = 0.f;

    int a_loff = (lane & 15) * SPe + ((lane >> 4) << 3);
    int b_loff = ((lane & 7) + ((lane & 16) >> 1)) * SPe + (lane & 8);

    int crow = tid >> 1, half = tid & 1;
    uint32_t drow = (uint32_t)(crow * ROWB + half * KCH);   // byte offset in tile
    int selem = half * (KCH / 2);                            // element offset in row
    int bvalid = (n0 + crow < N) ? 16 : 0;

    auto issue = [&](int ch, uint32_t stb) {
        int k0 = ch * KCH;
        const u16* pa = Ah + (size_t)(m0 + crow) * lda + k0 + selem;
        uint32_t d = stb + OFFAH + drow;
#pragma unroll
        for (int c = 0; c < CHK; c++) cpa16(d + c * 16, pa + c * 8, 16);
        pa = Al + (size_t)(m0 + crow) * lda + k0 + selem;
        d = stb + OFFAL + drow;
#pragma unroll
        for (int c = 0; c < CHK; c++) cpa16(d + c * 16, pa + c * 8, 16);
        size_t bo = bvalid ? ((size_t)(n0 + crow) * ldb + k0 + selem) : 0;
        const u16* pb = Bh + bo;
        d = stb + OFFBH + drow;
#pragma unroll
        for (int c = 0; c < CHK; c++) cpa16(d + c * 16, pb + (bvalid ? c * 8 : 0), bvalid);
        if (PASSES == 3) {
            pb = Bl + bo;
            d = stb + OFFBL + drow;
#pragma unroll
            for (int c = 0; c < CHK; c++) cpa16(d + c * 16, pb + (bvalid ? c * 8 : 0), bvalid);
        }
    };

    issue(0, sb);
    CP_COMMIT();

    for (int ch = 0; ch < nch; ch++) {
        if (ch + 1 < nch) issue(ch + 1, sb + ((ch + 1) & 1) * STAGEB);
        CP_COMMIT();
        CP_WAIT1();
        __syncthreads();

        uint32_t base = sb + (ch & 1) * STAGEB;
        uint32_t aHi = base + OFFAH + 2u * (uint32_t)((wm * 64) * SPe + a_loff);
        uint32_t aLo = base + OFFAL + 2u * (uint32_t)((wm * 64) * SPe + a_loff);
        uint32_t bHi = base + OFFBH + 2u * (uint32_t)((wn * 32) * SPe + b_loff);
        uint32_t bLo = base + OFFBL + 2u * (uint32_t)((wn * 32) * SPe + b_loff);

#pragma unroll
        for (int ks = 0; ks < KS; ks++) {
            uint32_t koff = (uint32_t)(ks * 32);
            uint32_t bh[2][4], bl[2][4], af[4][4];
#pragma unroll
            for (int jj = 0; jj < 2; jj++) {
                ldsm4(bh[jj], bHi + (uint32_t)(jj * 32 * SPe) + koff);
                if (PASSES == 3) ldsm4(bl[jj], bLo + (uint32_t)(jj * 32 * SPe) + koff);
            }
#pragma unroll
            for (int i = 0; i < 4; i++)
                ldsm4(af[i], aHi + (uint32_t)(i * 32 * SPe) + koff);
#pragma unroll
            for (int i = 0; i < 4; i++)
#pragma unroll
                for (int j = 0; j < 4; j++) {
                    mmaT<FP16>(acc[i][j], af[i], &bh[j >> 1][(j & 1) * 2]);
                    if (PASSES == 3)
                        mmaT<FP16>(acc[i][j], af[i], &bl[j >> 1][(j & 1) * 2]);
                }
#pragma unroll
            for (int i = 0; i < 4; i++)
                ldsm4(af[i], aLo + (uint32_t)(i * 32 * SPe) + koff);
#pragma unroll
            for (int i = 0; i < 4; i++)
#pragma unroll
                for (int j = 0; j < 4; j++)
                    mmaT<FP16>(acc[i][j], af[i], &bh[j >> 1][(j & 1) * 2]);
        }
        __syncthreads();
    }

    {
        float* Cs = (float*)smem;
        int g = lane >> 2, t4 = lane & 3;
#pragma unroll
        for (int i = 0; i < 4; i++)
#pragma unroll
            for (int j = 0; j < 4; j++) {
                int r = wm * 64 + i * 16 + g;
                int c = wn * 32 + j * 8 + t4 * 2;
                *(float2*)&Cs[r * CS_LD + c]       = make_float2(acc[i][j][0], acc[i][j][1]);
                *(float2*)&Cs[(r + 8) * CS_LD + c] = make_float2(acc[i][j][2], acc[i][j][3]);
            }
    }
    __syncthreads();
    {
        const float* Cs = (const float*)smem;
        int c4 = lane << 2;
#pragma unroll
        for (int i = 0; i < 16; i++) {
            int r = i * 8 + wid;
            if (n0 + c4 < N) {
                float4 v = *(const float4*)&Cs[r * CS_LD + c4];
                v.x *= alpha; v.y *= alpha; v.z *= alpha; v.w *= alpha;
                if (bias) {
                    float4 bv = *(const float4*)(bias + n0 + c4);
                    v.x += bv.x; v.y += bv.y; v.z += bv.z; v.w += bv.w;
                }
                size_t off = (size_t)(m0 + r) * ldc + n0 + c4;
                if (Cf) *(float4*)(Cf + off) = v;
                if (Ch) {
                    uint64_t hv, lv; split4T<OUTF16>(v, hv, lv);
                    *(uint2*)(Ch + off) = make_uint2((uint32_t)hv, (uint32_t)(hv >> 32));
                    *(uint2*)(Cl + off) = make_uint2((uint32_t)lv, (uint32_t)(lv >> 32));
                }
            }
        }
    }
}

// ---------------- split kernels ----------------
template<int FP16>
__global__ void split_plain(const float4* __restrict__ src,
                            uint2* __restrict__ dh, uint2* __restrict__ dl, int n4)
{
    int i = blockIdx.x * blockDim.x + threadIdx.x;
    if (i < n4) {
        uint64_t h, l; split4T<FP16>(src[i], h, l);
        dh[i] = make_uint2((uint32_t)h, (uint32_t)(h >> 32));
        dl[i] = make_uint2((uint32_t)l, (uint32_t)(l >> 32));
    }
}

__global__ void split_trK(const float* __restrict__ src,
                          u16* __restrict__ dh, u16* __restrict__ dl)
{
    int i = blockIdx.x * blockDim.x + threadIdx.x;
    int d = i & (QS_ - 1);
    int c = (i >> 7) & (KVRANK_ - 1);
    int h = i >> 16;
    float v = src[((size_t)h * QS_ + d) * KVRANK_ + c];
    split1T<1>(v, dh[i], dl[i]);     // fp16
}

// ---------------- pointwise kernels ----------------
__device__ __forceinline__ float block_reduce_sum(float v, float* red) {
    int tid = threadIdx.x;
    for (int o = 16; o; o >>= 1) v += __shfl_xor_sync(0xffffffffu, v, o);
    if ((tid & 31) == 0) red[tid >> 5] = v;
    __syncthreads();
    if (tid < 32) {
        float w = (tid < (int)(blockDim.x >> 5)) ? red[tid] : 0.f;
        for (int o = 16; o; o >>= 1) w += __shfl_xor_sync(0xffffffffu, w, o);
        red[tid] = w;
    }
    __syncthreads();
    float r = red[0];
    __syncthreads();
    return r;
}

__global__ void rmsnorm_split_kernel(const float* __restrict__ in,
                                     u16* __restrict__ oh, u16* __restrict__ ol,
                                     const float* __restrict__ scale, int N)
{
    __shared__ float red[32];
    int r = blockIdx.x;
    const float* pi = in + (size_t)r * N;
    float ss = 0.f;
    for (int c = threadIdx.x; c < N; c += blockDim.x) { float v = pi[c]; ss += v * v; }
    ss = block_reduce_sum(ss, red);
    float inv = rsqrtf(ss / (float)N + 1e-6f);
    for (int c = threadIdx.x; c < N; c += blockDim.x)
        split1T<1>(pi[c] * inv * scale[c], oh[(size_t)r * N + c], ol[(size_t)r * N + c]);  // fp16
}

__device__ __forceinline__ void rope_angle(int s, int j, float* sn, float* cs) {
    int f = j & 31;
    float invf = 1.0f / powf(10000.0f, (float)(2 * f) / 64.0f);
    sincosf((float)s * invf, sn, cs);
}

__global__ void kv_post_kernel(const float* __restrict__ kvraw,
                               const float* __restrict__ kscale,
                               u16* __restrict__ kfh, u16* __restrict__ kfl,
                               u16* __restrict__ kfTh, u16* __restrict__ kfTl)
{
    __shared__ float red[32];
    int t = blockIdx.x;
    int b = t >> 10, s = t & (SEQ_ - 1);
    const float* pi = kvraw + (size_t)t * CD_;
    float ss = 0.f;
    for (int c = threadIdx.x; c < KVRANK_; c += blockDim.x) { float v = pi[c]; ss += v * v; }
    ss = block_reduce_sum(ss, red);
    float inv = rsqrtf(ss / (float)KVRANK_ + 1e-6f);
    for (int c = threadIdx.x; c < KVRANK_; c += blockDim.x) {
        float v = pi[c] * inv * kscale[c];
        split1T<0>(v, kfh[(size_t)t * CD_ + c], kfl[(size_t)t * CD_ + c]);   // bf16 (stage 5 B)
        size_t to = ((size_t)b * KVRANK_ + c) * SEQ_ + s;
        split1T<1>(v, kfTh[to], kfTl[to]);                                   // fp16 (stage 6 B)
    }
    if (threadIdx.x < ROT_) {
        int j = threadIdx.x;
        float sn, cs; rope_angle(s, j, &sn, &cs);
        float xv = pi[KVRANK_ + j];
        float hr = (j < 32) ? -pi[KVRANK_ + j + 32] : pi[KVRANK_ + j - 32];
        split1T<0>(xv * cs + hr * sn,
                   kfh[(size_t)t * CD_ + KVRANK_ + j], kfl[(size_t)t * CD_ + KVRANK_ + j]);
    }
}

__global__ void q_post_kernel(const float* __restrict__ qfull,
                              u16* __restrict__ qah, u16* __restrict__ qal)
{
    int t = blockIdx.x;
    int h = threadIdx.x >> 6, j = threadIdx.x & 63;
    int b = t >> 10, s = t & (SEQ_ - 1);
    const float* src = qfull + (size_t)t * QUP_ + h * (QS_ + ROT_) + QS_;
    float xv = src[j];
    float hr = (j < 32) ? -src[j + 32] : src[j - 32];
    float sn, cs; rope_angle(s, j, &sn, &cs);
    size_t o = ((size_t)(b * H_ + h) * SEQ_ + s) * CD_ + KVRANK_ + j;
    split1T<0>(xv * cs + hr * sn, qah[o], qal[o]);                           // bf16 (stage 5 A)
}

__global__ void softmax_kernel(const float* __restrict__ scores,
                               u16* __restrict__ Ph, u16* __restrict__ Pl)
{
    __shared__ float red[32];
    int s = blockIdx.x, bh = blockIdx.y;
    size_t base = ((size_t)bh * SEQ_ + s) * SEQ_;
    const float* row = scores + base;
    int L = s + 1;
    int tid = threadIdx.x;

    float m = -1e30f;
    for (int c = tid; c < L; c += blockDim.x) m = fmaxf(m, row[c]);
    for (int o = 16; o; o >>= 1) m = fmaxf(m, __shfl_xor_sync(0xffffffffu, m, o));
    if ((tid & 31) == 0) red[tid >> 5] = m;
    __syncthreads();
    if (tid < 32) {
        float w = (tid < (int)(blockDim.x >> 5)) ? red[tid] : -1e30f;
        for (int o = 16; o; o >>= 1) w = fmaxf(w, __shfl_xor_sync(0xffffffffu, w, o));
        red[tid] = w;
    }
    __syncthreads();
    m = red[0];
    __syncthreads();

    float sum = 0.f;
    for (int c = tid; c < L; c += blockDim.x) sum += expf(row[c] - m);
    sum = block_reduce_sum(sum, red);
    float inv = 1.f / sum;
    for (int c = tid; c < L; c += blockDim.x)
        split1T<1>(expf(row[c] - m) * inv, Ph[base + c], Pl[base + c]);      // fp16

    int end = ((s >> 7) + 1) << 7;
    for (int c = L + tid; c < end; c += blockDim.x) { Ph[base + c] = 0; Pl[base + c] = 0; }
}

// ---------------- host side ----------------
template<int FP16, int PASSES, int OUTF16>
static void launch_gemm(const u16* Ah, const u16* Al, const u16* Bh, const u16* Bl,
                        float* Cf, u16* Ch, u16* Cl, const float* bias,
                        int M, int N, int K, int lda, int ldb, int ldc,
                        long long sAo, long long sAi, long long sBo, long long sBi,
                        long long sCo, long long sCi, int zdiv, int nbatch,
                        float alpha, int causal, int klimit)
{
    dim3 grid((N + 127) / 128, M / 128, nbatch);
    gemm_bf<FP16, PASSES, OUTF16><<<grid, 256, cfg_smem(PASSES)>>>(
        Ah, Al, Bh, Bl, Cf, Ch, Cl, bias, M, N, K, lda, ldb, ldc,
        sAo, sAi, sBo, sBi, sCo, sCi, zdiv, alpha, causal, klimit);
}

#define GETP(var, sym) cudaGetSymbolAddress((void**)&var, sym)

extern "C" void kernel_launch(void* const* d_in, const int* in_sizes, int n_in,
                              void* d_out, int out_size)
{
    const float* x   = (const float*)d_in[0];
    const float* qdw = (const float*)d_in[3];
    const float* qdb = (const float*)d_in[4];
    const float* qns = (const float*)d_in[5];
    const float* quw = (const float*)d_in[6];
    const float* qub = (const float*)d_in[7];
    const float* kdw = (const float*)d_in[8];
    const float* kdb = (const float*)d_in[9];
    const float* kns = (const float*)d_in[10];
    const float* kuw = (const float*)d_in[11];
    const float* ow  = (const float*)d_in[12];
    const float* ob  = (const float*)d_in[13];
    float* out = (float*)d_out;

    cudaFuncSetAttribute(gemm_bf<1,2,1>, cudaFuncAttributeMaxDynamicSharedMemorySize, cfg_smem(2));
    cudaFuncSetAttribute(gemm_bf<1,2,0>, cudaFuncAttributeMaxDynamicSharedMemorySize, cfg_smem(2));
    cudaFuncSetAttribute(gemm_bf<0,3,0>, cudaFuncAttributeMaxDynamicSharedMemorySize, cfg_smem(3));

    float *qd, *kvraw, *qfull, *scr;
    GETP(qd, g_qd); GETP(kvraw, g_kvraw); GETP(qfull, g_qfull); GETP(scr, g_scr);

    u16 *xh,*xl,*qdwh,*qdwl,*quwh,*quwl,*kdwh,*kdwl,*owh,*owl,*kKTh,*kKTl,*kVh,*kVl;
    u16 *qnh,*qnl,*qfh,*qfl,*kfh,*kfl,*kfTh,*kfTl,*qah,*qal,*Ph,*Pl,*cch,*ccl,*cxh,*cxl;
    GETP(xh, s_xh); GETP(xl, s_xl);
    GETP(qdwh, s_qdwh); GETP(qdwl, s_qdwl);
    GETP(quwh, s_quwh); GETP(quwl, s_quwl);
    GETP(kdwh, s_kdwh); GETP(kdwl, s_kdwl);
    GETP(owh, s_owh);   GETP(owl, s_owl);
    GETP(kKTh, s_kKTh); GETP(kKTl, s_kKTl);
    GETP(kVh, s_kVh);   GETP(kVl, s_kVl);
    GETP(qnh, s_qnh);   GETP(qnl, s_qnl);
    GETP(qfh, s_qfh);   GETP(qfl, s_qfl);
    GETP(kfh, s_kfh);   GETP(kfl, s_kfl);
    GETP(kfTh, s_kfTh); GETP(kfTl, s_kfTl);
    GETP(qah, s_qah);   GETP(qal, s_qal);
    GETP(Ph, s_Ph);     GETP(Pl, s_Pl);
    GETP(cch, s_cch);   GETP(ccl, s_ccl);
    GETP(cxh, s_cxh);   GETP(cxl, s_cxl);

    const float inv_sqrt_d = 1.0f / sqrtf(192.0f);

    auto spl_f16 = [](const float* s, u16* dh, u16* dl, size_t n) {
        int n4 = (int)(n / 4);
        split_plain<1><<<(n4 + 255) / 256, 256>>>((const float4*)s, (uint2*)dh, (uint2*)dl, n4);
    };
    spl_f16(x,   xh,   xl,   (size_t)T_ * DIM_);
    spl_f16(qdw, qdwh, qdwl, (size_t)QRANK_ * DIM_);
    spl_f16(quw, quwh, quwl, (size_t)QUP_ * QRANK_);
    spl_f16(kdw, kdwh, kdwl, (size_t)CD_ * DIM_);
    spl_f16(ow,  owh,  owl,  (size_t)DIM_ * DIM_);
    spl_f16(kuw + (size_t)H_ * QS_ * KVRANK_, kVh, kVl, (size_t)H_ * VD_ * KVRANK_);
    split_trK<<<(H_ * KVRANK_ * QS_) / 256, 256>>>(kuw, kKTh, kKTl);

    // 1) q_down -> fp32   [fp16 2-pass, KC=64]
    launch_gemm<1,2,1>(xh, xl, qdwh, qdwl, qd, nullptr, nullptr, qdb,
                       T_, QRANK_, DIM_, DIM_, DIM_, QRANK_,
                       0, 0, 0, 0, 0, 0, 1, 1, 1.f, 0, 0);
    rmsnorm_split_kernel<<<T_, 256>>>(qd, qnh, qnl, qns, QRANK_);

    // 2) q_up -> fp32 + fp16 hi/lo
    launch_gemm<1,2,1>(qnh, qnl, quwh, quwl, qfull, qfh, qfl, qub,
                       T_, QUP_, QRANK_, QRANK_, QRANK_, QUP_,
                       0, 0, 0, 0, 0, 0, 1, 1, 1.f, 0, 0);

    // 3) kv_down -> fp32
    launch_gemm<1,2,1>(xh, xl, kdwh, kdwl, kvraw, nullptr, nullptr, kdb,
                       T_, CD_, DIM_, DIM_, DIM_, CD_,
                       0, 0, 0, 0, 0, 0, 1, 1, 1.f, 0, 0);
    kv_post_kernel<<<T_, 256>>>(kvraw, kns, kfh, kfl, kfTh, kfTl);
    q_post_kernel<<<T_, 1024>>>(qfull, qah, qal);

    // 4) absorbed q -> bf16 out   [K=128 -> 2 chunks of 64]
    launch_gemm<1,2,0>(qfh, qfl, kKTh, kKTl, nullptr, qah, qal, nullptr,
                       SEQ_, KVRANK_, QS_, QUP_, QS_, CD_,
                       (long long)SEQ_ * QUP_, (long long)(QS_ + ROT_),
                       0, (long long)KVRANK_ * QS_,
                       (long long)H_ * SEQ_ * CD_, (long long)SEQ_ * CD_,
                       H_, BS_ * H_, 1.f, 0, 0);

    // 5) scores (causal)   [bf16 3-pass, KC=32 — unchanged]
    launch_gemm<0,3,0>(qah, qal, kfh, kfl, scr, nullptr, nullptr, nullptr,
                       SEQ_, SEQ_, CD_, CD_, CD_, SEQ_,
                       (long long)H_ * SEQ_ * CD_, (long long)SEQ_ * CD_,
                       (long long)SEQ_ * CD_, 0,
                       (long long)H_ * SEQ_ * SEQ_, (long long)SEQ_ * SEQ_,
                       H_, BS_ * H_, inv_sqrt_d, 1, 0);

    softmax_kernel<<<dim3(SEQ_, BS_ * H_), 256>>>(scr, Ph, Pl);

    // 6) ctx_c (klimit)
    launch_gemm<1,2,1>(Ph, Pl, kfTh, kfTl, nullptr, cch, ccl, nullptr,
                       SEQ_, KVRANK_, SEQ_, SEQ_, SEQ_, KVRANK_,
                       (long long)H_ * SEQ_ * SEQ_, (long long)SEQ_ * SEQ_,
                       (long long)KVRANK_ * SEQ_, 0,
                       (long long)H_ * SEQ_ * KVRANK_, (long long)SEQ_ * KVRANK_,
                       H_, BS_ * H_, 1.f, 0, 1);

    // 7) v-proj
    launch_gemm<1,2,1>(cch, ccl, kVh, kVl, nullptr, cxh, cxl, nullptr,
                       SEQ_, VD_, KVRANK_, KVRANK_, KVRANK_, DIM_,
                       (long long)H_ * SEQ_ * KVRANK_, (long long)SEQ_ * KVRANK_,
                       0, (long long)VD_ * KVRANK_,
                       (long long)SEQ_ * DIM_, (long long)VD_,
                       H_, BS_ * H_, 1.f, 0, 0);

    // 8) out
    launch_gemm<1,2,1>(cxh, cxl, owh, owl, out, nullptr, nullptr, ob,
                       T_, DIM_, DIM_, DIM_, DIM_, DIM_,
                       0, 0, 0, 0, 0, 0, 1, 1, 1.f, 0, 0);
}

// round 17
// speedup vs baseline: 1.0516x; 1.0516x over previous
#include <cuda_runtime.h>
#include <cuda_bf16.h>
#include <cuda_fp16.h>
#include <cstdint>
#include <cmath>

#define BS_     2
#define SEQ_    1024
#define DIM_    2048
#define H_      16
#define QRANK_  768
#define KVRANK_ 512
#define QS_     128
#define ROT_    64
#define CD_     576
#define VD_     128
#define T_      2048
#define QUP_    3072

typedef unsigned short u16;

__device__ float g_qd   [(size_t)T_ * QRANK_];
__device__ float g_kvraw[(size_t)T_ * CD_];
__device__ float g_qfull[(size_t)T_ * QUP_];
__device__ float g_scr  [(size_t)BS_ * H_ * SEQ_ * SEQ_];

#define DECL2(name, n) __device__ __align__(16) u16 name##h[(size_t)(n)]; \
                       __device__ __align__(16) u16 name##l[(size_t)(n)];
DECL2(s_x,    T_ * DIM_)                  // fp16
DECL2(s_qdw,  QRANK_ * DIM_)              // fp16
DECL2(s_quw,  QUP_ * QRANK_)              // fp16
DECL2(s_kdw,  CD_ * DIM_)                 // fp16
DECL2(s_ow,   DIM_ * DIM_)                // fp16
DECL2(s_kKT,  H_ * KVRANK_ * QS_)         // fp16
DECL2(s_kV,   H_ * VD_ * KVRANK_)         // fp16
DECL2(s_qn,   T_ * QRANK_)                // fp16
DECL2(s_qf,   T_ * QUP_)                  // fp16
DECL2(s_kf,   T_ * CD_)                   // bf16 (B of stage 5)
DECL2(s_kfT,  BS_ * KVRANK_ * SEQ_)       // fp16
DECL2(s_qa,   (size_t)BS_ * H_ * SEQ_ * CD_)    // bf16 (A of stage 5)
DECL2(s_P,    (size_t)BS_ * H_ * SEQ_ * SEQ_)   // fp16
DECL2(s_cc,   (size_t)BS_ * H_ * SEQ_ * KVRANK_)// fp16
DECL2(s_cx,   T_ * DIM_)                  // fp16

__device__ __forceinline__ uint32_t smem_u32(const void* p) {
    uint32_t a;
    asm("{ .reg .u64 t; cvta.to.shared.u64 t, %1; cvt.u32.u64 %0, t; }" : "=r"(a) : "l"(p));
    return a;
}
__device__ __forceinline__ void ldsm4(uint32_t* r, uint32_t addr) {
    asm volatile("ldmatrix.sync.aligned.m8n8.x4.shared.b16 {%0,%1,%2,%3}, [%4];"
        : "=r"(r[0]), "=r"(r[1]), "=r"(r[2]), "=r"(r[3]) : "r"(addr));
}
template<int FP16>
__device__ __forceinline__ void mmaT(float* c, const uint32_t* a, const uint32_t* b) {
    if (FP16)
        asm volatile("mma.sync.aligned.m16n8k16.row.col.f32.f16.f16.f32 "
            "{%0,%1,%2,%3}, {%4,%5,%6,%7}, {%8,%9}, {%0,%1,%2,%3};"
            : "+f"(c[0]), "+f"(c[1]), "+f"(c[2]), "+f"(c[3])
            : "r"(a[0]), "r"(a[1]), "r"(a[2]), "r"(a[3]), "r"(b[0]), "r"(b[1]));
    else
        asm volatile("mma.sync.aligned.m16n8k16.row.col.f32.bf16.bf16.f32 "
            "{%0,%1,%2,%3}, {%4,%5,%6,%7}, {%8,%9}, {%0,%1,%2,%3};"
            : "+f"(c[0]), "+f"(c[1]), "+f"(c[2]), "+f"(c[3])
            : "r"(a[0]), "r"(a[1]), "r"(a[2]), "r"(a[3]), "r"(b[0]), "r"(b[1]));
}
__device__ __forceinline__ void cpa16(uint32_t dst, const void* src, int sz) {
    asm volatile("cp.async.cg.shared.global [%0], [%1], 16, %2;"
        :: "r"(dst), "l"(src), "r"(sz) : "memory");
}
#define CP_COMMIT() asm volatile("cp.async.commit_group;" ::: "memory")
template<int N>
__device__ __forceinline__ void cpwaitN() {
    asm volatile("cp.async.wait_group %0;" :: "n"(N) : "memory");
}

template<int FP16>
__device__ __forceinline__ void split1T(float v, u16& h, u16& l) {
    if (FP16) {
        __half hb = __float2half_rn(v);
        h = __half_as_ushort(hb);
        l = __half_as_ushort(__float2half_rn(v - __half2float(hb)));
    } else {
        __nv_bfloat16 hb = __float2bfloat16(v);
        h = __bfloat16_as_ushort(hb);
        l = __bfloat16_as_ushort(__float2bfloat16(v - __bfloat162float(hb)));
    }
}
template<int FP16>
__device__ __forceinline__ void split4T(float4 v, uint64_t& hi, uint64_t& lo) {
    u16 h0,h1,h2,h3,l0,l1,l2,l3;
    split1T<FP16>(v.x,h0,l0); split1T<FP16>(v.y,h1,l1);
    split1T<FP16>(v.z,h2,l2); split1T<FP16>(v.w,h3,l3);
    hi = (uint64_t)h0 | ((uint64_t)h1<<16) | ((uint64_t)h2<<32) | ((uint64_t)h3<<48);
    lo = (uint64_t)l0 | ((uint64_t)l1<<16) | ((uint64_t)l2<<32) | ((uint64_t)l3<<48);
}

#define CS_LD   132
#define KCH     32
#define SPe     40
#define ROWB    (SPe * 2)           // 80 B
#define TILEB   (128 * ROWB)        // 10240 B

// 2-pass: 3 tiles/stage (no Bl), 3-stage ring. 3-pass: 4 tiles/stage, 2-stage.
__host__ __device__ constexpr int cfg_nt(int passes)    { return passes == 2 ? 3 : 4; }
__host__ __device__ constexpr int cfg_nst(int passes)   { return passes == 2 ? 3 : 2; }
__host__ __device__ constexpr int cfg_stageb(int passes){ return cfg_nt(passes) * TILEB; }
__host__ __device__ constexpr int cfg_smem(int passes)  {
    int s = cfg_nst(passes) * cfg_stageb(passes);
    int e = 128 * CS_LD * 4;
    return s > e ? s : e;
}

// C = alpha * A x B^T + bias ; A:[M,K] hi/lo, B:[N,K] hi/lo, k-contiguous
template<int FP16, int PASSES, int OUTF16>
__global__ __launch_bounds__(256, 2) void gemm_bf(
    const u16* __restrict__ Ah, const u16* __restrict__ Al,
    const u16* __restrict__ Bh, const u16* __restrict__ Bl,
    float* __restrict__ Cf, u16* __restrict__ Ch, u16* __restrict__ Cl,
    const float* __restrict__ bias,
    int M, int N, int K, int lda, int ldb, int ldc,
    long long sAo, long long sAi, long long sBo, long long sBi,
    long long sCo, long long sCi, int zdiv,
    float alpha, int causal, int klimit)
{
    constexpr int NST    = cfg_nst(PASSES);
    constexpr int STAGEB = cfg_stageb(PASSES);
    constexpr int OFFAH = 0, OFFAL = TILEB, OFFBH = 2 * TILEB, OFFBL = 3 * TILEB;

    int z = blockIdx.z;
    int zo = z / zdiv, zi = z - zo * zdiv;
    Ah += zo * sAo + zi * sAi;  Al += zo * sAo + zi * sAi;
    Bh += zo * sBo + zi * sBi;  if (PASSES == 3) Bl += zo * sBo + zi * sBi;
    long long co = zo * sCo + zi * sCi;
    if (Cf) Cf += co;
    if (Ch) { Ch += co; Cl += co; }

    int m0 = blockIdx.y * 128, n0 = blockIdx.x * 128;
    if (causal && n0 > m0) return;
    int kmax = klimit ? min(K, m0 + 128) : K;
    int nch = kmax / KCH;

    extern __shared__ char smem[];
    uint32_t sb = smem_u32(smem);
    int tid = threadIdx.x, wid = tid >> 5, lane = tid & 31;
    int wm = wid & 1, wn = wid >> 1;

    float acc[4][4][4];
#pragma unroll
    for (int i = 0; i < 4; i++)
#pragma unroll
        for (int j = 0; j < 4; j++)
#pragma unroll
            for (int q = 0; q < 4; q++) acc[i][j][q] = 0.f;

    int a_loff = (lane & 15) * SPe + ((lane >> 4) << 3);
    int b_loff = ((lane & 7) + ((lane & 16) >> 1)) * SPe + (lane & 8);

    int crow = tid >> 1, half = tid & 1;
    uint32_t drow = (uint32_t)(crow * ROWB + half * 32);     // byte offset in tile
    int selem = half * 16;                                   // element offset in row
    int bvalid = (n0 + crow < N) ? 16 : 0;

    auto issue = [&](int ch, uint32_t stb) {
        int k0 = ch * KCH;
        const u16* pa = Ah + (size_t)(m0 + crow) * lda + k0 + selem;
        uint32_t d = stb + OFFAH + drow;
        cpa16(d, pa, 16);       cpa16(d + 16, pa + 8, 16);
        pa = Al + (size_t)(m0 + crow) * lda + k0 + selem;
        d = stb + OFFAL + drow;
        cpa16(d, pa, 16);       cpa16(d + 16, pa + 8, 16);
        size_t bo = bvalid ? ((size_t)(n0 + crow) * ldb + k0 + selem) : 0;
        const u16* pb = Bh + bo;
        d = stb + OFFBH + drow;
        cpa16(d, pb, bvalid);   cpa16(d + 16, pb + (bvalid ? 8 : 0), bvalid);
        if (PASSES == 3) {
            pb = Bl + bo;
            d = stb + OFFBL + drow;
            cpa16(d, pb, bvalid); cpa16(d + 16, pb + (bvalid ? 8 : 0), bvalid);
        }
    };

    // prefetch NST-1 chunks
#pragma unroll
    for (int i = 0; i < NST - 1; i++) {
        if (i < nch) issue(i, sb + (i % NST) * STAGEB);
        CP_COMMIT();
    }

    for (int ch = 0; ch < nch; ch++) {
        int nx = ch + NST - 1;
        if (nx < nch) issue(nx, sb + (nx % NST) * STAGEB);
        CP_COMMIT();
        cpwaitN<NST - 1>();
        __syncthreads();

        uint32_t base = sb + (ch % NST) * STAGEB;
        uint32_t aHi = base + OFFAH + 2u * (uint32_t)((wm * 64) * SPe + a_loff);
        uint32_t aLo = base + OFFAL + 2u * (uint32_t)((wm * 64) * SPe + a_loff);
        uint32_t bHi = base + OFFBH + 2u * (uint32_t)((wn * 32) * SPe + b_loff);
        uint32_t bLo = base + OFFBL + 2u * (uint32_t)((wn * 32) * SPe + b_loff);

#pragma unroll
        for (int ks = 0; ks < 2; ks++) {
            uint32_t koff = (uint32_t)(ks * 32);
            uint32_t bh[2][4], bl[2][4], af[4][4];
#pragma unroll
            for (int jj = 0; jj < 2; jj++) {
                ldsm4(bh[jj], bHi + (uint32_t)(jj * 32 * SPe) + koff);
                if (PASSES == 3) ldsm4(bl[jj], bLo + (uint32_t)(jj * 32 * SPe) + koff);
            }
#pragma unroll
            for (int i = 0; i < 4; i++)
                ldsm4(af[i], aHi + (uint32_t)(i * 32 * SPe) + koff);
#pragma unroll
            for (int i = 0; i < 4; i++)
#pragma unroll
                for (int j = 0; j < 4; j++) {
                    mmaT<FP16>(acc[i][j], af[i], &bh[j >> 1][(j & 1) * 2]);
                    if (PASSES == 3)
                        mmaT<FP16>(acc[i][j], af[i], &bl[j >> 1][(j & 1) * 2]);
                }
#pragma unroll
            for (int i = 0; i < 4; i++)
                ldsm4(af[i], aLo + (uint32_t)(i * 32 * SPe) + koff);
#pragma unroll
            for (int i = 0; i < 4; i++)
#pragma unroll
                for (int j = 0; j < 4; j++)
                    mmaT<FP16>(acc[i][j], af[i], &bh[j >> 1][(j & 1) * 2]);
        }
        __syncthreads();
    }

    {
        float* Cs = (float*)smem;
        int g = lane >> 2, t4 = lane & 3;
#pragma unroll
        for (int i = 0; i < 4; i++)
#pragma unroll
            for (int j = 0; j < 4; j++) {
                int r = wm * 64 + i * 16 + g;
                int c = wn * 32 + j * 8 + t4 * 2;
                *(float2*)&Cs[r * CS_LD + c]       = make_float2(acc[i][j][0], acc[i][j][1]);
                *(float2*)&Cs[(r + 8) * CS_LD + c] = make_float2(acc[i][j][2], acc[i][j][3]);
            }
    }
    __syncthreads();
    {
        const float* Cs = (const float*)smem;
        int c4 = lane << 2;
#pragma unroll
        for (int i = 0; i < 16; i++) {
            int r = i * 8 + wid;
            if (n0 + c4 < N) {
                float4 v = *(const float4*)&Cs[r * CS_LD + c4];
                v.x *= alpha; v.y *= alpha; v.z *= alpha; v.w *= alpha;
                if (bias) {
                    float4 bv = *(const float4*)(bias + n0 + c4);
                    v.x += bv.x; v.y += bv.y; v.z += bv.z; v.w += bv.w;
                }
                size_t off = (size_t)(m0 + r) * ldc + n0 + c4;
                if (Cf) *(float4*)(Cf + off) = v;
                if (Ch) {
                    uint64_t hv, lv; split4T<OUTF16>(v, hv, lv);
                    *(uint2*)(Ch + off) = make_uint2((uint32_t)hv, (uint32_t)(hv >> 32));
                    *(uint2*)(Cl + off) = make_uint2((uint32_t)lv, (uint32_t)(lv >> 32));
                }
            }
        }
    }
}

// ---------------- split kernels ----------------
template<int FP16>
__global__ void split_plain(const float4* __restrict__ src,
                            uint2* __restrict__ dh, uint2* __restrict__ dl, int n4)
{
    int i = blockIdx.x * blockDim.x + threadIdx.x;
    if (i < n4) {
        uint64_t h, l; split4T<FP16>(src[i], h, l);
        dh[i] = make_uint2((uint32_t)h, (uint32_t)(h >> 32));
        dl[i] = make_uint2((uint32_t)l, (uint32_t)(l >> 32));
    }
}

__global__ void split_trK(const float* __restrict__ src,
                          u16* __restrict__ dh, u16* __restrict__ dl)
{
    int i = blockIdx.x * blockDim.x + threadIdx.x;
    int d = i & (QS_ - 1);
    int c = (i >> 7) & (KVRANK_ - 1);
    int h = i >> 16;
    float v = src[((size_t)h * QS_ + d) * KVRANK_ + c];
    split1T<1>(v, dh[i], dl[i]);     // fp16
}

// ---------------- pointwise kernels ----------------
__device__ __forceinline__ float block_reduce_sum(float v, float* red) {
    int tid = threadIdx.x;
    for (int o = 16; o; o >>= 1) v += __shfl_xor_sync(0xffffffffu, v, o);
    if ((tid & 31) == 0) red[tid >> 5] = v;
    __syncthreads();
    if (tid < 32) {
        float w = (tid < (int)(blockDim.x >> 5)) ? red[tid] : 0.f;
        for (int o = 16; o; o >>= 1) w += __shfl_xor_sync(0xffffffffu, w, o);
        red[tid] = w;
    }
    __syncthreads();
    float r = red[0];
    __syncthreads();
    return r;
}

__global__ void rmsnorm_split_kernel(const float* __restrict__ in,
                                     u16* __restrict__ oh, u16* __restrict__ ol,
                                     const float* __restrict__ scale, int N)
{
    __shared__ float red[32];
    int r = blockIdx.x;
    const float* pi = in + (size_t)r * N;
    float ss = 0.f;
    for (int c = threadIdx.x; c < N; c += blockDim.x) { float v = pi[c]; ss += v * v; }
    ss = block_reduce_sum(ss, red);
    float inv = rsqrtf(ss / (float)N + 1e-6f);
    for (int c = threadIdx.x; c < N; c += blockDim.x)
        split1T<1>(pi[c] * inv * scale[c], oh[(size_t)r * N + c], ol[(size_t)r * N + c]);  // fp16
}

__device__ __forceinline__ void rope_angle(int s, int j, float* sn, float* cs) {
    int f = j & 31;
    float invf = 1.0f / powf(10000.0f, (float)(2 * f) / 64.0f);
    sincosf((float)s * invf, sn, cs);
}

__global__ void kv_post_kernel(const float* __restrict__ kvraw,
                               const float* __restrict__ kscale,
                               u16* __restrict__ kfh, u16* __restrict__ kfl,
                               u16* __restrict__ kfTh, u16* __restrict__ kfTl)
{
    __shared__ float red[32];
    int t = blockIdx.x;
    int b = t >> 10, s = t & (SEQ_ - 1);
    const float* pi = kvraw + (size_t)t * CD_;
    float ss = 0.f;
    for (int c = threadIdx.x; c < KVRANK_; c += blockDim.x) { float v = pi[c]; ss += v * v; }
    ss = block_reduce_sum(ss, red);
    float inv = rsqrtf(ss / (float)KVRANK_ + 1e-6f);
    for (int c = threadIdx.x; c < KVRANK_; c += blockDim.x) {
        float v = pi[c] * inv * kscale[c];
        split1T<0>(v, kfh[(size_t)t * CD_ + c], kfl[(size_t)t * CD_ + c]);   // bf16 (stage 5 B)
        size_t to = ((size_t)b * KVRANK_ + c) * SEQ_ + s;
        split1T<1>(v, kfTh[to], kfTl[to]);                                   // fp16 (stage 6 B)
    }
    if (threadIdx.x < ROT_) {
        int j = threadIdx.x;
        float sn, cs; rope_angle(s, j, &sn, &cs);
        float xv = pi[KVRANK_ + j];
        float hr = (j < 32) ? -pi[KVRANK_ + j + 32] : pi[KVRANK_ + j - 32];
        split1T<0>(xv * cs + hr * sn,
                   kfh[(size_t)t * CD_ + KVRANK_ + j], kfl[(size_t)t * CD_ + KVRANK_ + j]);
    }
}

__global__ void q_post_kernel(const float* __restrict__ qfull,
                              u16* __restrict__ qah, u16* __restrict__ qal)
{
    int t = blockIdx.x;
    int h = threadIdx.x >> 6, j = threadIdx.x & 63;
    int b = t >> 10, s = t & (SEQ_ - 1);
    const float* src = qfull + (size_t)t * QUP_ + h * (QS_ + ROT_) + QS_;
    float xv = src[j];
    float hr = (j < 32) ? -src[j + 32] : src[j - 32];
    float sn, cs; rope_angle(s, j, &sn, &cs);
    size_t o = ((size_t)(b * H_ + h) * SEQ_ + s) * CD_ + KVRANK_ + j;
    split1T<0>(xv * cs + hr * sn, qah[o], qal[o]);                           // bf16 (stage 5 A)
}

__global__ void softmax_kernel(const float* __restrict__ scores,
                               u16* __restrict__ Ph, u16* __restrict__ Pl)
{
    __shared__ float red[32];
    int s = blockIdx.x, bh = blockIdx.y;
    size_t base = ((size_t)bh * SEQ_ + s) * SEQ_;
    const float* row = scores + base;
    int L = s + 1;
    int tid = threadIdx.x;

    float m = -1e30f;
    for (int c = tid; c < L; c += blockDim.x) m = fmaxf(m, row[c]);
    for (int o = 16; o; o >>= 1) m = fmaxf(m, __shfl_xor_sync(0xffffffffu, m, o));
    if ((tid & 31) == 0) red[tid >> 5] = m;
    __syncthreads();
    if (tid < 32) {
        float w = (tid < (int)(blockDim.x >> 5)) ? red[tid] : -1e30f;
        for (int o = 16; o; o >>= 1) w = fmaxf(w, __shfl_xor_sync(0xffffffffu, w, o));
        red[tid] = w;
    }
    __syncthreads();
    m = red[0];
    __syncthreads();

    float sum = 0.f;
    for (int c = tid; c < L; c += blockDim.x) sum += expf(row[c] - m);
    sum = block_reduce_sum(sum, red);
    float inv = 1.f / sum;
    for (int c = tid; c < L; c += blockDim.x)
        split1T<1>(expf(row[c] - m) * inv, Ph[base + c], Pl[base + c]);      // fp16

    int end = ((s >> 7) + 1) << 7;
    for (int c = L + tid; c < end; c += blockDim.x) { Ph[base + c] = 0; Pl[base + c] = 0; }
}

// ---------------- host side ----------------
template<int FP16, int PASSES, int OUTF16>
static void launch_gemm(const u16* Ah, const u16* Al, const u16* Bh, const u16* Bl,
                        float* Cf, u16* Ch, u16* Cl, const float* bias,
                        int M, int N, int K, int lda, int ldb, int ldc,
                        long long sAo, long long sAi, long long sBo, long long sBi,
                        long long sCo, long long sCi, int zdiv, int nbatch,
                        float alpha, int causal, int klimit)
{
    dim3 grid((N + 127) / 128, M / 128, nbatch);
    gemm_bf<FP16, PASSES, OUTF16><<<grid, 256, cfg_smem(PASSES)>>>(
        Ah, Al, Bh, Bl, Cf, Ch, Cl, bias, M, N, K, lda, ldb, ldc,
        sAo, sAi, sBo, sBi, sCo, sCi, zdiv, alpha, causal, klimit);
}

#define GETP(var, sym) cudaGetSymbolAddress((void**)&var, sym)

extern "C" void kernel_launch(void* const* d_in, const int* in_sizes, int n_in,
                              void* d_out, int out_size)
{
    const float* x   = (const float*)d_in[0];
    const float* qdw = (const float*)d_in[3];
    const float* qdb = (const float*)d_in[4];
    const float* qns = (const float*)d_in[5];
    const float* quw = (const float*)d_in[6];
    const float* qub = (const float*)d_in[7];
    const float* kdw = (const float*)d_in[8];
    const float* kdb = (const float*)d_in[9];
    const float* kns = (const float*)d_in[10];
    const float* kuw = (const float*)d_in[11];
    const float* ow  = (const float*)d_in[12];
    const float* ob  = (const float*)d_in[13];
    float* out = (float*)d_out;

    cudaFuncSetAttribute(gemm_bf<1,2,1>, cudaFuncAttributeMaxDynamicSharedMemorySize, cfg_smem(2));
    cudaFuncSetAttribute(gemm_bf<1,2,0>, cudaFuncAttributeMaxDynamicSharedMemorySize, cfg_smem(2));
    cudaFuncSetAttribute(gemm_bf<0,3,0>, cudaFuncAttributeMaxDynamicSharedMemorySize, cfg_smem(3));

    float *qd, *kvraw, *qfull, *scr;
    GETP(qd, g_qd); GETP(kvraw, g_kvraw); GETP(qfull, g_qfull); GETP(scr, g_scr);

    u16 *xh,*xl,*qdwh,*qdwl,*quwh,*quwl,*kdwh,*kdwl,*owh,*owl,*kKTh,*kKTl,*kVh,*kVl;
    u16 *qnh,*qnl,*qfh,*qfl,*kfh,*kfl,*kfTh,*kfTl,*qah,*qal,*Ph,*Pl,*cch,*ccl,*cxh,*cxl;
    GETP(xh, s_xh); GETP(xl, s_xl);
    GETP(qdwh, s_qdwh); GETP(qdwl, s_qdwl);
    GETP(quwh, s_quwh); GETP(quwl, s_quwl);
    GETP(kdwh, s_kdwh); GETP(kdwl, s_kdwl);
    GETP(owh, s_owh);   GETP(owl, s_owl);
    GETP(kKTh, s_kKTh); GETP(kKTl, s_kKTl);
    GETP(kVh, s_kVh);   GETP(kVl, s_kVl);
    GETP(qnh, s_qnh);   GETP(qnl, s_qnl);
    GETP(qfh, s_qfh);   GETP(qfl, s_qfl);
    GETP(kfh, s_kfh);   GETP(kfl, s_kfl);
    GETP(kfTh, s_kfTh); GETP(kfTl, s_kfTl);
    GETP(qah, s_qah);   GETP(qal, s_qal);
    GETP(Ph, s_Ph);     GETP(Pl, s_Pl);
    GETP(cch, s_cch);   GETP(ccl, s_ccl);
    GETP(cxh, s_cxh);   GETP(cxl, s_cxl);

    const float inv_sqrt_d = 1.0f / sqrtf(192.0f);

    auto spl_f16 = [](const float* s, u16* dh, u16* dl, size_t n) {
        int n4 = (int)(n / 4);
        split_plain<1><<<(n4 + 255) / 256, 256>>>((const float4*)s, (uint2*)dh, (uint2*)dl, n4);
    };
    spl_f16(x,   xh,   xl,   (size_t)T_ * DIM_);
    spl_f16(qdw, qdwh, qdwl, (size_t)QRANK_ * DIM_);
    spl_f16(quw, quwh, quwl, (size_t)QUP_ * QRANK_);
    spl_f16(kdw, kdwh, kdwl, (size_t)CD_ * DIM_);
    spl_f16(ow,  owh,  owl,  (size_t)DIM_ * DIM_);
    spl_f16(kuw + (size_t)H_ * QS_ * KVRANK_, kVh, kVl, (size_t)H_ * VD_ * KVRANK_);
    split_trK<<<(H_ * KVRANK_ * QS_) / 256, 256>>>(kuw, kKTh, kKTl);

    // 1) q_down -> fp32   [fp16 2-pass, 3-stage pipeline]
    launch_gemm<1,2,1>(xh, xl, qdwh, qdwl, qd, nullptr, nullptr, qdb,
                       T_, QRANK_, DIM_, DIM_, DIM_, QRANK_,
                       0, 0, 0, 0, 0, 0, 1, 1, 1.f, 0, 0);
    rmsnorm_split_kernel<<<T_, 256>>>(qd, qnh, qnl, qns, QRANK_);

    // 2) q_up -> fp32 + fp16 hi/lo
    launch_gemm<1,2,1>(qnh, qnl, quwh, quwl, qfull, qfh, qfl, qub,
                       T_, QUP_, QRANK_, QRANK_, QRANK_, QUP_,
                       0, 0, 0, 0, 0, 0, 1, 1, 1.f, 0, 0);

    // 3) kv_down -> fp32
    launch_gemm<1,2,1>(xh, xl, kdwh, kdwl, kvraw, nullptr, nullptr, kdb,
                       T_, CD_, DIM_, DIM_, DIM_, CD_,
                       0, 0, 0, 0, 0, 0, 1, 1, 1.f, 0, 0);
    kv_post_kernel<<<T_, 256>>>(kvraw, kns, kfh, kfl, kfTh, kfTl);
    q_post_kernel<<<T_, 1024>>>(qfull, qah, qal);

    // 4) absorbed q -> bf16 out
    launch_gemm<1,2,0>(qfh, qfl, kKTh, kKTl, nullptr, qah, qal, nullptr,
                       SEQ_, KVRANK_, QS_, QUP_, QS_, CD_,
                       (long long)SEQ_ * QUP_, (long long)(QS_ + ROT_),
                       0, (long long)KVRANK_ * QS_,
                       (long long)H_ * SEQ_ * CD_, (long long)SEQ_ * CD_,
                       H_, BS_ * H_, 1.f, 0, 0);

    // 5) scores (causal)   [bf16 3-pass, 2-stage — unchanged]
    launch_gemm<0,3,0>(qah, qal, kfh, kfl, scr, nullptr, nullptr, nullptr,
                       SEQ_, SEQ_, CD_, CD_, CD_, SEQ_,
                       (long long)H_ * SEQ_ * CD_, (long long)SEQ_ * CD_,
                       (long long)SEQ_ * CD_, 0,
                       (long long)H_ * SEQ_ * SEQ_, (long long)SEQ_ * SEQ_,
                       H_, BS_ * H_, inv_sqrt_d, 1, 0);

    softmax_kernel<<<dim3(SEQ_, BS_ * H_), 256>>>(scr, Ph, Pl);

    // 6) ctx_c (klimit)
    launch_gemm<1,2,1>(Ph, Pl, kfTh, kfTl, nullptr, cch, ccl, nullptr,
                       SEQ_, KVRANK_, SEQ_, SEQ_, SEQ_, KVRANK_,
                       (long long)H_ * SEQ_ * SEQ_, (long long)SEQ_ * SEQ_,
                       (long long)KVRANK_ * SEQ_, 0,
                       (long long)H_ * SEQ_ * KVRANK_, (long long)SEQ_ * KVRANK_,
                       H_, BS_ * H_, 1.f, 0, 1);

    // 7) v-proj
    launch_gemm<1,2,1>(cch, ccl, kVh, kVl, nullptr, cxh, cxl, nullptr,
                       SEQ_, VD_, KVRANK_, KVRANK_, KVRANK_, DIM_,
                       (long long)H_ * SEQ_ * KVRANK_, (long long)SEQ_ * KVRANK_,
                       0, (long long)VD_ * KVRANK_,
                       (long long)SEQ_ * DIM_, (long long)VD_,
                       H_, BS_ * H_, 1.f, 0, 0);

    // 8) out
    launch_gemm<1,2,1>(cxh, cxl, owh, owl, out, nullptr, nullptr, ob,
                       T_, DIM_, DIM_, DIM_, DIM_, DIM_,
                       0, 0, 0, 0, 0, 0, 1, 1, 1.f, 0, 0);
}